// round 16
// baseline (speedup 1.0000x reference)
#include <cuda_runtime.h>
#include <cstdint>
#include <math.h>

// Problem constants
#define kD    1024
#define kE    256
#define kNE   2048
#define kCH   4
#define kM1   16384
#define kMR   65536
#define NCHUNK 4
#define M1C   (kM1 / NCHUNK)   // 4096 gemm0 rows per chunk
#define MRC   (kMR / NCHUNK)   // 16384 code rows per chunk
#define AM_PAD 32768           // argmax dummy smem: caps ~6 blocks/SM to leave room for gemm0

// -------- scratch (static device globals; no allocations) --------
__device__ float  g_cz[(size_t)kM1 * kD];          // 64 MB
__device__ float  g_P[(size_t)kCH * kNE * kD];     // 32 MB
__device__ float  g_esq[kNE];
__device__ float  g_esq_mm[2];                     // [max, min]
__device__ float  g_czsq[kMR];
__device__ float  g_lv[kMR];                       // winner squared distance per row
__device__ int    g_idx[kMR];

// ------------------------- f32x2 packed FMA helpers -------------------------
#define FFMA2(d, a, b) asm("fma.rn.f32x2 %0, %1, %2, %0;" : "+l"(d) : "l"(a), "l"(b))
#define PACK2(d, f)    asm("mov.b64 %0, {%1, %1};" : "=l"(d) : "r"(__float_as_uint(f)))
#define UNPACK2(lo, hi, d) asm("mov.b64 {%0, %1}, %2;" : "=r"(lo), "=r"(hi) : "l"(d))

// ------------------------- threefry2x32 (key = [0, 42]) -------------------------
__device__ __forceinline__ uint32_t rotl32(uint32_t x, int r) { return (x << r) | (x >> (32 - r)); }
__device__ __forceinline__ void threefry2x32_42(uint32_t x0, uint32_t x1,
                                                uint32_t& o0, uint32_t& o1) {
    const uint32_t ks0 = 0u, ks1 = 42u;
    const uint32_t ks2 = 0x1BD11BDAu ^ ks0 ^ ks1;
    x0 += ks0; x1 += ks1;
#define TF_R(r) { x0 += x1; x1 = rotl32(x1, (r)); x1 ^= x0; }
    TF_R(13) TF_R(15) TF_R(26) TF_R(6)
    x0 += ks1; x1 += ks2 + 1u;
    TF_R(17) TF_R(29) TF_R(16) TF_R(24)
    x0 += ks2; x1 += ks0 + 2u;
    TF_R(13) TF_R(15) TF_R(26) TF_R(6)
    x0 += ks0; x1 += ks1 + 3u;
    TF_R(17) TF_R(29) TF_R(16) TF_R(24)
    x0 += ks1; x1 += ks2 + 4u;
    TF_R(13) TF_R(15) TF_R(26) TF_R(6)
    x0 += ks2; x1 += ks0 + 5u;
#undef TF_R
    o0 = x0; o1 = x1;
}
__device__ __forceinline__ float uniform_at(uint32_t j) {
    uint32_t r0, r1;
    threefry2x32_42(0u, j, r0, r1);
    uint32_t bits = r0 ^ r1;
    float f = __uint_as_float((bits >> 9) | 0x3f800000u) - 1.0f;
    const float TINY = 1.17549435e-38f;
    return fmaxf(TINY, f + TINY);
}
__device__ __forceinline__ float gumbel_of_u(float u) { return -logf(-logf(u)); }

// ======================= GEMM0 (R14/R15 champion): split-plane B, 2 CTA/SM ======================
__global__ void __launch_bounds__(256, 2)
gemm0_kernel(const float* __restrict__ A, const float* __restrict__ Bm,
             const float* __restrict__ bias, float* __restrict__ C, int N, int K) {
    __shared__ float As[2][16][132];
    __shared__ float Bs[2][16][2][80];
    const int tid = threadIdx.x;
    const int bx = blockIdx.x, by = blockIdx.y;
    const int tx = tid & 15, ty = tid >> 4;
    const int ar = tid >> 2, ac = (tid & 3) << 2;
    const int br = tid >> 5;               // 0..7
    const int q  = tid & 31;               // B column-group 0..31 (col = q*4)
    const int bpl = q & 1;                 // plane
    const int boff = (q >> 1) * 4;         // offset within plane

    unsigned long long acc2[8][4];
#pragma unroll
    for (int i = 0; i < 8; i++)
#pragma unroll
        for (int j = 0; j < 4; j++) acc2[i][j] = 0ull;

    const int S = K / 16;
    float4 a4[2], b4[2];
#pragma unroll
    for (int h = 0; h < 2; h++) {
        a4[h] = *reinterpret_cast<const float4*>(&A[(size_t)(by * 128 + ar + h * 64) * K + ac]);
        b4[h] = *reinterpret_cast<const float4*>(&Bm[(size_t)(br + h * 8) * N + bx * 128 + q * 4]);
    }
#pragma unroll
    for (int h = 0; h < 2; h++) {
        As[0][ac + 0][ar + h * 64] = a4[h].x;
        As[0][ac + 1][ar + h * 64] = a4[h].y;
        As[0][ac + 2][ar + h * 64] = a4[h].z;
        As[0][ac + 3][ar + h * 64] = a4[h].w;
        *reinterpret_cast<float4*>(&Bs[0][br + h * 8][bpl][boff]) = b4[h];
    }
    __syncthreads();

    for (int s = 0; s < S; s++) {
        const int cur = s & 1;
        if (s + 1 < S) {
            int k1 = (s + 1) * 16;
#pragma unroll
            for (int h = 0; h < 2; h++) {
                a4[h] = *reinterpret_cast<const float4*>(&A[(size_t)(by * 128 + ar + h * 64) * K + k1 + ac]);
                b4[h] = *reinterpret_cast<const float4*>(&Bm[(size_t)(k1 + br + h * 8) * N + bx * 128 + q * 4]);
            }
        }
#pragma unroll
        for (int kk = 0; kk < 16; kk++) {
            float4 av0 = *reinterpret_cast<const float4*>(&As[cur][kk][ty * 8]);
            float4 av1 = *reinterpret_cast<const float4*>(&As[cur][kk][ty * 8 + 4]);
            ulonglong2 q0 = *reinterpret_cast<const ulonglong2*>(&Bs[cur][kk][0][tx * 4]);
            ulonglong2 q1 = *reinterpret_cast<const ulonglong2*>(&Bs[cur][kk][1][tx * 4]);
            unsigned long long b2[4] = {q0.x, q0.y, q1.x, q1.y};
            unsigned long long ap[8];
            PACK2(ap[0], av0.x); PACK2(ap[1], av0.y); PACK2(ap[2], av0.z); PACK2(ap[3], av0.w);
            PACK2(ap[4], av1.x); PACK2(ap[5], av1.y); PACK2(ap[6], av1.z); PACK2(ap[7], av1.w);
#pragma unroll
            for (int i = 0; i < 8; i++)
#pragma unroll
                for (int j = 0; j < 4; j++) FFMA2(acc2[i][j], ap[i], b2[j]);
        }
        if (s + 1 < S) {
            int nb = (s + 1) & 1;
#pragma unroll
            for (int h = 0; h < 2; h++) {
                As[nb][ac + 0][ar + h * 64] = a4[h].x;
                As[nb][ac + 1][ar + h * 64] = a4[h].y;
                As[nb][ac + 2][ar + h * 64] = a4[h].z;
                As[nb][ac + 3][ar + h * 64] = a4[h].w;
                *reinterpret_cast<float4*>(&Bs[nb][br + h * 8][bpl][boff]) = b4[h];
            }
        }
        __syncthreads();
    }

#pragma unroll
    for (int i = 0; i < 8; i++) {
        int row = by * 128 + ty * 8 + i;
        int col = bx * 128 + tx * 8;
        float a[8];
#pragma unroll
        for (int j = 0; j < 4; j++) {
            uint32_t lo, hi;
            UNPACK2(lo, hi, acc2[i][j]);
            a[2 * j] = __uint_as_float(lo);
            a[2 * j + 1] = __uint_as_float(hi);
        }
#pragma unroll
        for (int j = 0; j < 8; j += 4) {
            float4 v;
            v.x = a[j + 0] + bias[col + j + 0];
            v.y = a[j + 1] + bias[col + j + 1];
            v.z = a[j + 2] + bias[col + j + 2];
            v.w = a[j + 3] + bias[col + j + 3];
            *reinterpret_cast<float4*>(&C[(size_t)row * N + col + j]) = v;
        }
    }
}

// ======================= P = E @ W1_ch (2 CTA/SM) =======================
__global__ void __launch_bounds__(256, 2)
pgemm_kernel(const float* __restrict__ E, const float* __restrict__ W1,
             float* __restrict__ P) {
    __shared__ float As[2][16][132];
    __shared__ float Bs[2][16][132];
    const int tid = threadIdx.x;
    const int bx = blockIdx.x, by = blockIdx.y, ch = blockIdx.z;
    const int tx = tid & 15, ty = tid >> 4;
    const int ar = tid >> 2, ac = (tid & 3) << 2;
    const int br = tid >> 5, bc = (tid & 31) << 2;
    const float* Bm = W1 + (size_t)ch * kE * kD;

    unsigned long long acc2[8][4];
#pragma unroll
    for (int i = 0; i < 8; i++)
#pragma unroll
        for (int j = 0; j < 4; j++) acc2[i][j] = 0ull;

    const int S = kE / 16;
    float4 a4[2], b4[2];
#pragma unroll
    for (int h = 0; h < 2; h++) {
        a4[h] = *reinterpret_cast<const float4*>(&E[(size_t)(by * 128 + ar + h * 64) * kE + ac]);
        b4[h] = *reinterpret_cast<const float4*>(&Bm[(size_t)(br + h * 8) * kD + bx * 128 + bc]);
    }
#pragma unroll
    for (int h = 0; h < 2; h++) {
        As[0][ac + 0][ar + h * 64] = a4[h].x;
        As[0][ac + 1][ar + h * 64] = a4[h].y;
        As[0][ac + 2][ar + h * 64] = a4[h].z;
        As[0][ac + 3][ar + h * 64] = a4[h].w;
        *reinterpret_cast<float4*>(&Bs[0][br + h * 8][bc]) = b4[h];
    }
    __syncthreads();

    for (int s = 0; s < S; s++) {
        const int cur = s & 1;
        if (s + 1 < S) {
            int k1 = (s + 1) * 16;
#pragma unroll
            for (int h = 0; h < 2; h++) {
                a4[h] = *reinterpret_cast<const float4*>(&E[(size_t)(by * 128 + ar + h * 64) * kE + k1 + ac]);
                b4[h] = *reinterpret_cast<const float4*>(&Bm[(size_t)(k1 + br + h * 8) * kD + bx * 128 + bc]);
            }
        }
#pragma unroll
        for (int kk = 0; kk < 16; kk++) {
            float4 av0 = *reinterpret_cast<const float4*>(&As[cur][kk][ty * 8]);
            float4 av1 = *reinterpret_cast<const float4*>(&As[cur][kk][ty * 8 + 4]);
            const unsigned long long* bp =
                reinterpret_cast<const unsigned long long*>(&Bs[cur][kk][tx * 8]);
            unsigned long long b2[4];
#pragma unroll
            for (int j = 0; j < 4; j++) b2[j] = bp[j];
            unsigned long long ap[8];
            PACK2(ap[0], av0.x); PACK2(ap[1], av0.y); PACK2(ap[2], av0.z); PACK2(ap[3], av0.w);
            PACK2(ap[4], av1.x); PACK2(ap[5], av1.y); PACK2(ap[6], av1.z); PACK2(ap[7], av1.w);
#pragma unroll
            for (int i = 0; i < 8; i++)
#pragma unroll
                for (int j = 0; j < 4; j++) FFMA2(acc2[i][j], ap[i], b2[j]);
        }
        if (s + 1 < S) {
            int nb = (s + 1) & 1;
#pragma unroll
            for (int h = 0; h < 2; h++) {
                As[nb][ac + 0][ar + h * 64] = a4[h].x;
                As[nb][ac + 1][ar + h * 64] = a4[h].y;
                As[nb][ac + 2][ar + h * 64] = a4[h].z;
                As[nb][ac + 3][ar + h * 64] = a4[h].w;
                *reinterpret_cast<float4*>(&Bs[nb][br + h * 8][bc]) = b4[h];
            }
        }
        __syncthreads();
    }

    float* Pout = P + (size_t)ch * kNE * kD;
#pragma unroll
    for (int i = 0; i < 8; i++) {
        int row = by * 128 + ty * 8 + i;
        int col = bx * 128 + tx * 8;
#pragma unroll
        for (int j = 0; j < 4; j++) {
            uint32_t lo, hi;
            UNPACK2(lo, hi, acc2[i][j]);
            float2 v;
            v.x = __uint_as_float(lo);
            v.y = __uint_as_float(hi);
            *reinterpret_cast<float2*>(&Pout[(size_t)row * kD + col + 2 * j]) = v;
        }
    }
}

// ======================= row squared norms (4 rows per warp, double accumulate) ================
__global__ void __launch_bounds__(256)
rowsq4_kernel(const float* __restrict__ X, float* __restrict__ out) {
    int warp = threadIdx.x >> 5, lane = threadIdx.x & 31;
    int row0 = blockIdx.x * 32 + warp * 4;
    float4 va[4][2];
#pragma unroll
    for (int r = 0; r < 4; r++) {
        const float4* p = reinterpret_cast<const float4*>(X + (size_t)(row0 + r) * kE);
        va[r][0] = p[lane];
        va[r][1] = p[lane + 32];
    }
    double s[4];
#pragma unroll
    for (int r = 0; r < 4; r++) {
        double s0 = (double)va[r][0].x * va[r][0].x + (double)va[r][0].y * va[r][0].y;
        double s1 = (double)va[r][0].z * va[r][0].z + (double)va[r][0].w * va[r][0].w;
        double s2 = (double)va[r][1].x * va[r][1].x + (double)va[r][1].y * va[r][1].y;
        double s3 = (double)va[r][1].z * va[r][1].z + (double)va[r][1].w * va[r][1].w;
        s[r] = (s0 + s1) + (s2 + s3);
    }
#pragma unroll
    for (int o = 16; o > 0; o >>= 1) {
#pragma unroll
        for (int r = 0; r < 4; r++) s[r] += __shfl_xor_sync(0xffffffffu, s[r], o);
    }
    if (lane < 4) out[row0 + lane] = (float)s[lane];
}

// esq max/min (single block)
__global__ void __launch_bounds__(256)
esq_minmax_kernel(const float* __restrict__ esq, float* __restrict__ mm) {
    int t = threadIdx.x;
    float mx = -INFINITY, mn = INFINITY;
    for (int i = t; i < kNE; i += 256) {
        float v = esq[i];
        mx = fmaxf(mx, v);
        mn = fminf(mn, v);
    }
    __shared__ float sMx[256], sMn[256];
    sMx[t] = mx; sMn[t] = mn;
    __syncthreads();
    for (int o = 128; o > 0; o >>= 1) {
        if (t < o) {
            sMx[t] = fmaxf(sMx[t], sMx[t + o]);
            sMn[t] = fminf(sMn[t], sMn[t + o]);
        }
        __syncthreads();
    }
    if (t == 0) { mm[0] = sMx[0]; mm[1] = sMn[0]; }
}

// ======================= argmax (R15 numerics) + occupancy cap via dummy smem ==================
// Dynamic smem pad (unused) caps resident blocks/SM so a gemm0 CTA can co-reside:
// the two kernels use disjoint pipes (ALU/MUFU vs FMA), so spatial sharing hides argmax.
__global__ void __launch_bounds__(128)
argmax5_kernel(const float* __restrict__ cz, const float* __restrict__ E,
               const float* __restrict__ czsq, const float* __restrict__ esq,
               const float* __restrict__ esq_mm, int* __restrict__ outidx,
               float* __restrict__ outlv, int rowBase) {
    extern __shared__ char am_pad[];   // unused occupancy limiter
    (void)am_pad;
    int row = blockIdx.x;
    int t = threadIdx.x;
    int warp = t >> 5, lane = t & 31;

    __shared__ float sCz[kE];
    __shared__ float sWU[4];
    __shared__ float sWBv[4];
    __shared__ float sWLv[4];
    __shared__ int   sWBi[4];

    {
        float2 v = *reinterpret_cast<const float2*>(&cz[(size_t)row * kE + t * 2]);
        sCz[t * 2] = v.x; sCz[t * 2 + 1] = v.y;
    }
    float cs = czsq[row];
    float emax = esq_mm[0], emin = esq_mm[1];

    float uu[16];
    float umax = 0.0f;
    uint32_t base = (uint32_t)(rowBase + row) * (uint32_t)kNE;
#pragma unroll
    for (int i = 0; i < 16; i++) {
        uu[i] = uniform_at(base + (uint32_t)(i * 128 + t));
        umax = fmaxf(umax, uu[i]);
    }
#pragma unroll
    for (int o = 16; o > 0; o >>= 1)
        umax = fmaxf(umax, __shfl_xor_sync(0xffffffffu, umax, o));
    if (lane == 0) sWU[warp] = umax;
    __syncthreads();   // covers sCz + sWU
    float u_top = fmaxf(fmaxf(sWU[0], sWU[1]), fmaxf(sWU[2], sWU[3]));

    float D = 4.04f * sqrtf(cs) * sqrtf(emax) + (emax - emin) + 1e-3f;
    float g_top = gumbel_of_u(u_top);
    float thr_g = g_top - D - 1e-4f;
    float u_req = expf(-expf(-thr_g)) * 0.9999f;

    float best = -INFINITY, bestlv = 0.0f;
    int bi = kNE;
#pragma unroll
    for (int i = 0; i < 16; i++) {
        if (uu[i] >= u_req) {
            int e = i * 128 + t;
            const float* Er = E + (size_t)e * kE;
            float acc = 0.0f;
#pragma unroll 16
            for (int k = 0; k < kE; k++) acc = fmaf(sCz[k], Er[k], acc);
            float lv = (cs + esq[e]) - 2.0f * acc;
            float s = (lv - cs) + gumbel_of_u(uu[i]);
            if (s > best || (s == best && e < bi)) { best = s; bi = e; bestlv = lv; }
        }
    }
#pragma unroll
    for (int o = 16; o > 0; o >>= 1) {
        float ob = __shfl_xor_sync(0xffffffffu, best, o);
        int   oi = __shfl_xor_sync(0xffffffffu, bi, o);
        float ol = __shfl_xor_sync(0xffffffffu, bestlv, o);
        if (ob > best || (ob == best && oi < bi)) { best = ob; bi = oi; bestlv = ol; }
    }
    if (lane == 0) { sWBv[warp] = best; sWBi[warp] = bi; sWLv[warp] = bestlv; }
    __syncthreads();
    if (t == 0) {
        float b = sWBv[0]; int i0 = sWBi[0]; float l = sWLv[0];
#pragma unroll
        for (int w = 1; w < 4; w++) {
            if (sWBv[w] > b || (sWBv[w] == b && sWBi[w] < i0)) {
                b = sWBv[w]; i0 = sWBi[w]; l = sWLv[w];
            }
        }
        outidx[row] = i0;
        outlv[row] = l;
    }
}

// ======================= z_q gather =======================
__global__ void __launch_bounds__(256)
gather_zq_kernel(const float* __restrict__ P, const int* __restrict__ idx,
                 const float* __restrict__ b1, float* __restrict__ out) {
    int m = blockIdx.x;
    int c = threadIdx.x * 4;
    int4 id = *reinterpret_cast<const int4*>(&idx[m * 4]);
    float4 p0 = *reinterpret_cast<const float4*>(&P[((size_t)0 * kNE + id.x) * kD + c]);
    float4 p1 = *reinterpret_cast<const float4*>(&P[((size_t)1 * kNE + id.y) * kD + c]);
    float4 p2 = *reinterpret_cast<const float4*>(&P[((size_t)2 * kNE + id.z) * kD + c]);
    float4 p3 = *reinterpret_cast<const float4*>(&P[((size_t)3 * kNE + id.w) * kD + c]);
    float4 bb = *reinterpret_cast<const float4*>(&b1[c]);
    float4 v;
    v.x = ((p0.x + p1.x) + p2.x) + p3.x + bb.x;
    v.y = ((p0.y + p1.y) + p2.y) + p3.y + bb.y;
    v.z = ((p0.z + p1.z) + p2.z) + p3.z + bb.z;
    v.w = ((p0.w + p1.w) + p2.w) + p3.w + bb.w;
    size_t o = (size_t)m * kD + c;
    out[o + 0] = v.x; out[o + 1] = v.y; out[o + 2] = v.z; out[o + 3] = v.w;
}

// ------------------------- loss from winner lv: out[0] = 1.25 * sum(lv) / 2^24 -----------------
__global__ void __launch_bounds__(1024)
lvsum_kernel(const float* __restrict__ lv, float* __restrict__ out) {
    int t = threadIdx.x;
    double s = 0.0;
    for (int i = t; i < kMR; i += 1024) s += (double)lv[i];
    __shared__ double sd[1024];
    sd[t] = s;
    __syncthreads();
    for (int o = 512; o > 0; o >>= 1) {
        if (t < o) sd[t] += sd[t + o];
        __syncthreads();
    }
    if (t == 0) {
        float m = (float)(sd[0] / 16777216.0);
        out[0] = m + 0.25f * m;
    }
}

// ------------------------- launch (R15 schedule + priority sB + capped argmax) -----------------
extern "C" void kernel_launch(void* const* d_in, const int* in_sizes, int n_in,
                              void* d_out, int out_size) {
    const float* z  = (const float*)d_in[0];
    const float* W0 = (const float*)d_in[1];
    const float* b0 = (const float*)d_in[2];
    const float* W1 = (const float*)d_in[3];
    const float* b1 = (const float*)d_in[4];
    const float* E  = (const float*)d_in[5];
    float* out = (float*)d_out;

    float *p_cz, *p_esq, *p_esq_mm, *p_czsq, *p_P, *p_lv;
    int* p_idx;
    cudaGetSymbolAddress((void**)&p_cz, g_cz);
    cudaGetSymbolAddress((void**)&p_esq, g_esq);
    cudaGetSymbolAddress((void**)&p_esq_mm, g_esq_mm);
    cudaGetSymbolAddress((void**)&p_czsq, g_czsq);
    cudaGetSymbolAddress((void**)&p_idx, g_idx);
    cudaGetSymbolAddress((void**)&p_P, g_P);
    cudaGetSymbolAddress((void**)&p_lv, g_lv);

    static cudaStream_t sB = 0;
    static cudaEvent_t evFork, evEnd, evA[NCHUNK];
    static bool init_done = false;
    if (!init_done) {
        int loPri = 0, hiPri = 0;
        cudaDeviceGetStreamPriorityRange(&loPri, &hiPri);
        if (cudaStreamCreateWithPriority(&sB, cudaStreamNonBlocking, hiPri) != cudaSuccess)
            sB = 0;
        cudaEventCreateWithFlags(&evFork, cudaEventDisableTiming);
        cudaEventCreateWithFlags(&evEnd, cudaEventDisableTiming);
        for (int c = 0; c < NCHUNK; c++)
            cudaEventCreateWithFlags(&evA[c], cudaEventDisableTiming);
        init_done = true;
    }

    int zoff = out_size - kM1 * kD;
    float* zq = out + (zoff > 0 ? zoff : 0);
    bool do_loss = (zoff >= 1);
    bool do_zq = (out_size >= kM1 * kD);

    // fork sB from the capture stream
    cudaEventRecord(evFork, 0);
    cudaStreamWaitEvent(sB, evFork, 0);

    // sB: codebook-side precomputes (independent of cz)
    pgemm_kernel<<<dim3(kD / 128, kNE / 128, kCH), 256, 0, sB>>>(E, W1, p_P);
    rowsq4_kernel<<<kNE / 32, 256, 0, sB>>>(E, p_esq);
    esq_minmax_kernel<<<1, 256, 0, sB>>>(p_esq, p_esq_mm);

    // stream0: gemm0 chunks; sB consumes each chunk (rowsq -> argmax -> gather)
    for (int c = 0; c < NCHUNK; c++) {
        gemm0_kernel<<<dim3(kD / 128, M1C / 128), 256>>>(
            z + (size_t)c * M1C * kD, W0, b0, p_cz + (size_t)c * M1C * kD, kD, kD);
        cudaEventRecord(evA[c], 0);
        cudaStreamWaitEvent(sB, evA[c], 0);
        rowsq4_kernel<<<MRC / 32, 256, 0, sB>>>(p_cz + (size_t)c * M1C * kD,
                                                p_czsq + (size_t)c * MRC);
        argmax5_kernel<<<MRC, 128, AM_PAD, sB>>>(p_cz + (size_t)c * M1C * kD, E,
                                                 p_czsq + (size_t)c * MRC, p_esq, p_esq_mm,
                                                 p_idx + (size_t)c * MRC,
                                                 p_lv + (size_t)c * MRC, c * MRC);
        if (do_zq)
            gather_zq_kernel<<<M1C, 256, 0, sB>>>(p_P, p_idx + (size_t)c * MRC, b1,
                                                  zq + (size_t)c * M1C * kD);
    }
    if (do_loss)
        lvsum_kernel<<<1, 1024, 0, sB>>>(p_lv, out);

    // join sB back into the capture stream
    cudaEventRecord(evEnd, sB);
    cudaStreamWaitEvent(0, evEnd, 0);
}

// round 17
// speedup vs baseline: 1.1516x; 1.1516x over previous
#include <cuda_runtime.h>
#include <cstdint>
#include <math.h>

// Problem constants
#define kD    1024
#define kE    256
#define kNE   2048
#define kCH   4
#define kM1   16384
#define kMR   65536
#define NCHUNK 4
#define M1C   (kM1 / NCHUNK)   // 4096 gemm0 rows per chunk
#define MRC   (kMR / NCHUNK)   // 16384 code rows per chunk

// -------- scratch (static device globals; no allocations) --------
__device__ float  g_cz[(size_t)kM1 * kD];          // 64 MB
__device__ float  g_P[(size_t)kCH * kNE * kD];     // 32 MB
__device__ float  g_esq[kNE];
__device__ float  g_esq_mm[2];                     // [max, min]
__device__ float  g_czsq[kMR];
__device__ float  g_lv[kMR];                       // winner squared distance per row
__device__ int    g_idx[kMR];

// ------------------------- f32x2 packed FMA helpers -------------------------
#define FFMA2(d, a, b) asm("fma.rn.f32x2 %0, %1, %2, %0;" : "+l"(d) : "l"(a), "l"(b))
#define PACK2(d, f)    asm("mov.b64 %0, {%1, %1};" : "=l"(d) : "r"(__float_as_uint(f)))
#define UNPACK2(lo, hi, d) asm("mov.b64 {%0, %1}, %2;" : "=r"(lo), "=r"(hi) : "l"(d))

// ------------------------- threefry2x32 (key = [0, 42]) -------------------------
__device__ __forceinline__ uint32_t rotl32(uint32_t x, int r) { return (x << r) | (x >> (32 - r)); }
__device__ __forceinline__ void threefry2x32_42(uint32_t x0, uint32_t x1,
                                                uint32_t& o0, uint32_t& o1) {
    const uint32_t ks0 = 0u, ks1 = 42u;
    const uint32_t ks2 = 0x1BD11BDAu ^ ks0 ^ ks1;
    x0 += ks0; x1 += ks1;
#define TF_R(r) { x0 += x1; x1 = rotl32(x1, (r)); x1 ^= x0; }
    TF_R(13) TF_R(15) TF_R(26) TF_R(6)
    x0 += ks1; x1 += ks2 + 1u;
    TF_R(17) TF_R(29) TF_R(16) TF_R(24)
    x0 += ks2; x1 += ks0 + 2u;
    TF_R(13) TF_R(15) TF_R(26) TF_R(6)
    x0 += ks0; x1 += ks1 + 3u;
    TF_R(17) TF_R(29) TF_R(16) TF_R(24)
    x0 += ks1; x1 += ks2 + 4u;
    TF_R(13) TF_R(15) TF_R(26) TF_R(6)
    x0 += ks2; x1 += ks0 + 5u;
#undef TF_R
    o0 = x0; o1 = x1;
}
__device__ __forceinline__ float uniform_at(uint32_t j) {
    uint32_t r0, r1;
    threefry2x32_42(0u, j, r0, r1);
    uint32_t bits = r0 ^ r1;
    float f = __uint_as_float((bits >> 9) | 0x3f800000u) - 1.0f;
    const float TINY = 1.17549435e-38f;
    return fmaxf(TINY, f + TINY);
}
__device__ __forceinline__ float gumbel_of_u(float u) { return -logf(-logf(u)); }

// ======================= GEMM0 (R15 + compile-time K, unroll-2 main loop) ======================
__global__ void __launch_bounds__(256, 2)
gemm0_kernel(const float* __restrict__ A, const float* __restrict__ Bm,
             const float* __restrict__ bias, float* __restrict__ C) {
    __shared__ float As[2][16][132];
    __shared__ float Bs[2][16][2][80];
    const int tid = threadIdx.x;
    const int bx = blockIdx.x, by = blockIdx.y;
    const int tx = tid & 15, ty = tid >> 4;
    const int ar = tid >> 2, ac = (tid & 3) << 2;
    const int br = tid >> 5;               // 0..7
    const int q  = tid & 31;               // B column-group 0..31 (col = q*4)
    const int bpl = q & 1;                 // plane
    const int boff = (q >> 1) * 4;         // offset within plane

    unsigned long long acc2[8][4];
#pragma unroll
    for (int i = 0; i < 8; i++)
#pragma unroll
        for (int j = 0; j < 4; j++) acc2[i][j] = 0ull;

    const int S = kD / 16;                 // compile-time 64
    float4 a4[2], b4[2];
#pragma unroll
    for (int h = 0; h < 2; h++) {
        a4[h] = *reinterpret_cast<const float4*>(&A[(size_t)(by * 128 + ar + h * 64) * kD + ac]);
        b4[h] = *reinterpret_cast<const float4*>(&Bm[(size_t)(br + h * 8) * kD + bx * 128 + q * 4]);
    }
#pragma unroll
    for (int h = 0; h < 2; h++) {
        As[0][ac + 0][ar + h * 64] = a4[h].x;
        As[0][ac + 1][ar + h * 64] = a4[h].y;
        As[0][ac + 2][ar + h * 64] = a4[h].z;
        As[0][ac + 3][ar + h * 64] = a4[h].w;
        *reinterpret_cast<float4*>(&Bs[0][br + h * 8][bpl][boff]) = b4[h];
    }
    __syncthreads();

#pragma unroll 2
    for (int s = 0; s < S; s++) {
        const int cur = s & 1;
        if (s + 1 < S) {
            int k1 = (s + 1) * 16;
#pragma unroll
            for (int h = 0; h < 2; h++) {
                a4[h] = *reinterpret_cast<const float4*>(&A[(size_t)(by * 128 + ar + h * 64) * kD + k1 + ac]);
                b4[h] = *reinterpret_cast<const float4*>(&Bm[(size_t)(k1 + br + h * 8) * kD + bx * 128 + q * 4]);
            }
        }
#pragma unroll
        for (int kk = 0; kk < 16; kk++) {
            float4 av0 = *reinterpret_cast<const float4*>(&As[cur][kk][ty * 8]);
            float4 av1 = *reinterpret_cast<const float4*>(&As[cur][kk][ty * 8 + 4]);
            ulonglong2 q0 = *reinterpret_cast<const ulonglong2*>(&Bs[cur][kk][0][tx * 4]);
            ulonglong2 q1 = *reinterpret_cast<const ulonglong2*>(&Bs[cur][kk][1][tx * 4]);
            unsigned long long b2[4] = {q0.x, q0.y, q1.x, q1.y};
            unsigned long long ap[8];
            PACK2(ap[0], av0.x); PACK2(ap[1], av0.y); PACK2(ap[2], av0.z); PACK2(ap[3], av0.w);
            PACK2(ap[4], av1.x); PACK2(ap[5], av1.y); PACK2(ap[6], av1.z); PACK2(ap[7], av1.w);
#pragma unroll
            for (int i = 0; i < 8; i++)
#pragma unroll
                for (int j = 0; j < 4; j++) FFMA2(acc2[i][j], ap[i], b2[j]);
        }
        if (s + 1 < S) {
            int nb = (s + 1) & 1;
#pragma unroll
            for (int h = 0; h < 2; h++) {
                As[nb][ac + 0][ar + h * 64] = a4[h].x;
                As[nb][ac + 1][ar + h * 64] = a4[h].y;
                As[nb][ac + 2][ar + h * 64] = a4[h].z;
                As[nb][ac + 3][ar + h * 64] = a4[h].w;
                *reinterpret_cast<float4*>(&Bs[nb][br + h * 8][bpl][boff]) = b4[h];
            }
        }
        __syncthreads();
    }

#pragma unroll
    for (int i = 0; i < 8; i++) {
        int row = by * 128 + ty * 8 + i;
        int col = bx * 128 + tx * 8;
        float a[8];
#pragma unroll
        for (int j = 0; j < 4; j++) {
            uint32_t lo, hi;
            UNPACK2(lo, hi, acc2[i][j]);
            a[2 * j] = __uint_as_float(lo);
            a[2 * j + 1] = __uint_as_float(hi);
        }
#pragma unroll
        for (int j = 0; j < 8; j += 4) {
            float4 v;
            v.x = a[j + 0] + bias[col + j + 0];
            v.y = a[j + 1] + bias[col + j + 1];
            v.z = a[j + 2] + bias[col + j + 2];
            v.w = a[j + 3] + bias[col + j + 3];
            *reinterpret_cast<float4*>(&C[(size_t)row * kD + col + j]) = v;
        }
    }
}

// ======================= P = E @ W1_ch (2 CTA/SM) =======================
__global__ void __launch_bounds__(256, 2)
pgemm_kernel(const float* __restrict__ E, const float* __restrict__ W1,
             float* __restrict__ P) {
    __shared__ float As[2][16][132];
    __shared__ float Bs[2][16][132];
    const int tid = threadIdx.x;
    const int bx = blockIdx.x, by = blockIdx.y, ch = blockIdx.z;
    const int tx = tid & 15, ty = tid >> 4;
    const int ar = tid >> 2, ac = (tid & 3) << 2;
    const int br = tid >> 5, bc = (tid & 31) << 2;
    const float* Bm = W1 + (size_t)ch * kE * kD;

    unsigned long long acc2[8][4];
#pragma unroll
    for (int i = 0; i < 8; i++)
#pragma unroll
        for (int j = 0; j < 4; j++) acc2[i][j] = 0ull;

    const int S = kE / 16;
    float4 a4[2], b4[2];
#pragma unroll
    for (int h = 0; h < 2; h++) {
        a4[h] = *reinterpret_cast<const float4*>(&E[(size_t)(by * 128 + ar + h * 64) * kE + ac]);
        b4[h] = *reinterpret_cast<const float4*>(&Bm[(size_t)(br + h * 8) * kD + bx * 128 + bc]);
    }
#pragma unroll
    for (int h = 0; h < 2; h++) {
        As[0][ac + 0][ar + h * 64] = a4[h].x;
        As[0][ac + 1][ar + h * 64] = a4[h].y;
        As[0][ac + 2][ar + h * 64] = a4[h].z;
        As[0][ac + 3][ar + h * 64] = a4[h].w;
        *reinterpret_cast<float4*>(&Bs[0][br + h * 8][bc]) = b4[h];
    }
    __syncthreads();

    for (int s = 0; s < S; s++) {
        const int cur = s & 1;
        if (s + 1 < S) {
            int k1 = (s + 1) * 16;
#pragma unroll
            for (int h = 0; h < 2; h++) {
                a4[h] = *reinterpret_cast<const float4*>(&E[(size_t)(by * 128 + ar + h * 64) * kE + k1 + ac]);
                b4[h] = *reinterpret_cast<const float4*>(&Bm[(size_t)(k1 + br + h * 8) * kD + bx * 128 + bc]);
            }
        }
#pragma unroll
        for (int kk = 0; kk < 16; kk++) {
            float4 av0 = *reinterpret_cast<const float4*>(&As[cur][kk][ty * 8]);
            float4 av1 = *reinterpret_cast<const float4*>(&As[cur][kk][ty * 8 + 4]);
            const unsigned long long* bp =
                reinterpret_cast<const unsigned long long*>(&Bs[cur][kk][tx * 8]);
            unsigned long long b2[4];
#pragma unroll
            for (int j = 0; j < 4; j++) b2[j] = bp[j];
            unsigned long long ap[8];
            PACK2(ap[0], av0.x); PACK2(ap[1], av0.y); PACK2(ap[2], av0.z); PACK2(ap[3], av0.w);
            PACK2(ap[4], av1.x); PACK2(ap[5], av1.y); PACK2(ap[6], av1.z); PACK2(ap[7], av1.w);
#pragma unroll
            for (int i = 0; i < 8; i++)
#pragma unroll
                for (int j = 0; j < 4; j++) FFMA2(acc2[i][j], ap[i], b2[j]);
        }
        if (s + 1 < S) {
            int nb = (s + 1) & 1;
#pragma unroll
            for (int h = 0; h < 2; h++) {
                As[nb][ac + 0][ar + h * 64] = a4[h].x;
                As[nb][ac + 1][ar + h * 64] = a4[h].y;
                As[nb][ac + 2][ar + h * 64] = a4[h].z;
                As[nb][ac + 3][ar + h * 64] = a4[h].w;
                *reinterpret_cast<float4*>(&Bs[nb][br + h * 8][bc]) = b4[h];
            }
        }
        __syncthreads();
    }

    float* Pout = P + (size_t)ch * kNE * kD;
#pragma unroll
    for (int i = 0; i < 8; i++) {
        int row = by * 128 + ty * 8 + i;
        int col = bx * 128 + tx * 8;
#pragma unroll
        for (int j = 0; j < 4; j++) {
            uint32_t lo, hi;
            UNPACK2(lo, hi, acc2[i][j]);
            float2 v;
            v.x = __uint_as_float(lo);
            v.y = __uint_as_float(hi);
            *reinterpret_cast<float2*>(&Pout[(size_t)row * kD + col + 2 * j]) = v;
        }
    }
}

// ======================= row squared norms (4 rows per warp, double accumulate) ================
__global__ void __launch_bounds__(256)
rowsq4_kernel(const float* __restrict__ X, float* __restrict__ out) {
    int warp = threadIdx.x >> 5, lane = threadIdx.x & 31;
    int row0 = blockIdx.x * 32 + warp * 4;
    float4 va[4][2];
#pragma unroll
    for (int r = 0; r < 4; r++) {
        const float4* p = reinterpret_cast<const float4*>(X + (size_t)(row0 + r) * kE);
        va[r][0] = p[lane];
        va[r][1] = p[lane + 32];
    }
    double s[4];
#pragma unroll
    for (int r = 0; r < 4; r++) {
        double s0 = (double)va[r][0].x * va[r][0].x + (double)va[r][0].y * va[r][0].y;
        double s1 = (double)va[r][0].z * va[r][0].z + (double)va[r][0].w * va[r][0].w;
        double s2 = (double)va[r][1].x * va[r][1].x + (double)va[r][1].y * va[r][1].y;
        double s3 = (double)va[r][1].z * va[r][1].z + (double)va[r][1].w * va[r][1].w;
        s[r] = (s0 + s1) + (s2 + s3);
    }
#pragma unroll
    for (int o = 16; o > 0; o >>= 1) {
#pragma unroll
        for (int r = 0; r < 4; r++) s[r] += __shfl_xor_sync(0xffffffffu, s[r], o);
    }
    if (lane < 4) out[row0 + lane] = (float)s[lane];
}

// esq max/min (single block)
__global__ void __launch_bounds__(256)
esq_minmax_kernel(const float* __restrict__ esq, float* __restrict__ mm) {
    int t = threadIdx.x;
    float mx = -INFINITY, mn = INFINITY;
    for (int i = t; i < kNE; i += 256) {
        float v = esq[i];
        mx = fmaxf(mx, v);
        mn = fminf(mn, v);
    }
    __shared__ float sMx[256], sMn[256];
    sMx[t] = mx; sMn[t] = mn;
    __syncthreads();
    for (int o = 128; o > 0; o >>= 1) {
        if (t < o) {
            sMx[t] = fmaxf(sMx[t], sMx[t + o]);
            sMn[t] = fminf(sMn[t], sMn[t + o]);
        }
        __syncthreads();
    }
    if (t == 0) { mm[0] = sMx[0]; mm[1] = sMn[0]; }
}

// ======================= argmax (R15): shuffle reductions, 2 barriers ===========================
__global__ void __launch_bounds__(128)
argmax5_kernel(const float* __restrict__ cz, const float* __restrict__ E,
               const float* __restrict__ czsq, const float* __restrict__ esq,
               const float* __restrict__ esq_mm, int* __restrict__ outidx,
               float* __restrict__ outlv, int rowBase) {
    int row = blockIdx.x;
    int t = threadIdx.x;
    int warp = t >> 5, lane = t & 31;

    __shared__ float sCz[kE];
    __shared__ float sWU[4];
    __shared__ float sWBv[4];
    __shared__ float sWLv[4];
    __shared__ int   sWBi[4];

    {
        float2 v = *reinterpret_cast<const float2*>(&cz[(size_t)row * kE + t * 2]);
        sCz[t * 2] = v.x; sCz[t * 2 + 1] = v.y;
    }
    float cs = czsq[row];
    float emax = esq_mm[0], emin = esq_mm[1];

    float uu[16];
    float umax = 0.0f;
    uint32_t base = (uint32_t)(rowBase + row) * (uint32_t)kNE;
#pragma unroll
    for (int i = 0; i < 16; i++) {
        uu[i] = uniform_at(base + (uint32_t)(i * 128 + t));
        umax = fmaxf(umax, uu[i]);
    }
#pragma unroll
    for (int o = 16; o > 0; o >>= 1)
        umax = fmaxf(umax, __shfl_xor_sync(0xffffffffu, umax, o));
    if (lane == 0) sWU[warp] = umax;
    __syncthreads();   // covers sCz + sWU
    float u_top = fmaxf(fmaxf(sWU[0], sWU[1]), fmaxf(sWU[2], sWU[3]));

    float D = 4.04f * sqrtf(cs) * sqrtf(emax) + (emax - emin) + 1e-3f;
    float g_top = gumbel_of_u(u_top);
    float thr_g = g_top - D - 1e-4f;
    float u_req = expf(-expf(-thr_g)) * 0.9999f;

    float best = -INFINITY, bestlv = 0.0f;
    int bi = kNE;
#pragma unroll
    for (int i = 0; i < 16; i++) {
        if (uu[i] >= u_req) {
            int e = i * 128 + t;
            const float* Er = E + (size_t)e * kE;
            float acc = 0.0f;
#pragma unroll 16
            for (int k = 0; k < kE; k++) acc = fmaf(sCz[k], Er[k], acc);
            float lv = (cs + esq[e]) - 2.0f * acc;
            float s = (lv - cs) + gumbel_of_u(uu[i]);
            if (s > best || (s == best && e < bi)) { best = s; bi = e; bestlv = lv; }
        }
    }
#pragma unroll
    for (int o = 16; o > 0; o >>= 1) {
        float ob = __shfl_xor_sync(0xffffffffu, best, o);
        int   oi = __shfl_xor_sync(0xffffffffu, bi, o);
        float ol = __shfl_xor_sync(0xffffffffu, bestlv, o);
        if (ob > best || (ob == best && oi < bi)) { best = ob; bi = oi; bestlv = ol; }
    }
    if (lane == 0) { sWBv[warp] = best; sWBi[warp] = bi; sWLv[warp] = bestlv; }
    __syncthreads();
    if (t == 0) {
        float b = sWBv[0]; int i0 = sWBi[0]; float l = sWLv[0];
#pragma unroll
        for (int w = 1; w < 4; w++) {
            if (sWBv[w] > b || (sWBv[w] == b && sWBi[w] < i0)) {
                b = sWBv[w]; i0 = sWBi[w]; l = sWLv[w];
            }
        }
        outidx[row] = i0;
        outlv[row] = l;
    }
}

// ======================= z_q gather =======================
__global__ void __launch_bounds__(256)
gather_zq_kernel(const float* __restrict__ P, const int* __restrict__ idx,
                 const float* __restrict__ b1, float* __restrict__ out) {
    int m = blockIdx.x;
    int c = threadIdx.x * 4;
    int4 id = *reinterpret_cast<const int4*>(&idx[m * 4]);
    float4 p0 = *reinterpret_cast<const float4*>(&P[((size_t)0 * kNE + id.x) * kD + c]);
    float4 p1 = *reinterpret_cast<const float4*>(&P[((size_t)1 * kNE + id.y) * kD + c]);
    float4 p2 = *reinterpret_cast<const float4*>(&P[((size_t)2 * kNE + id.z) * kD + c]);
    float4 p3 = *reinterpret_cast<const float4*>(&P[((size_t)3 * kNE + id.w) * kD + c]);
    float4 bb = *reinterpret_cast<const float4*>(&b1[c]);
    float4 v;
    v.x = ((p0.x + p1.x) + p2.x) + p3.x + bb.x;
    v.y = ((p0.y + p1.y) + p2.y) + p3.y + bb.y;
    v.z = ((p0.z + p1.z) + p2.z) + p3.z + bb.z;
    v.w = ((p0.w + p1.w) + p2.w) + p3.w + bb.w;
    size_t o = (size_t)m * kD + c;
    out[o + 0] = v.x; out[o + 1] = v.y; out[o + 2] = v.z; out[o + 3] = v.w;
}

// ------------------------- loss from winner lv: out[0] = 1.25 * sum(lv) / 2^24 -----------------
__global__ void __launch_bounds__(1024)
lvsum_kernel(const float* __restrict__ lv, float* __restrict__ out) {
    int t = threadIdx.x;
    double s = 0.0;
    for (int i = t; i < kMR; i += 1024) s += (double)lv[i];
    __shared__ double sd[1024];
    sd[t] = s;
    __syncthreads();
    for (int o = 512; o > 0; o >>= 1) {
        if (t < o) sd[t] += sd[t + o];
        __syncthreads();
    }
    if (t == 0) {
        float m = (float)(sd[0] / 16777216.0);
        out[0] = m + 0.25f * m;
    }
}

// ------------------------- launch (exact R15 schedule) -------------------------
extern "C" void kernel_launch(void* const* d_in, const int* in_sizes, int n_in,
                              void* d_out, int out_size) {
    const float* z  = (const float*)d_in[0];
    const float* W0 = (const float*)d_in[1];
    const float* b0 = (const float*)d_in[2];
    const float* W1 = (const float*)d_in[3];
    const float* b1 = (const float*)d_in[4];
    const float* E  = (const float*)d_in[5];
    float* out = (float*)d_out;

    float *p_cz, *p_esq, *p_esq_mm, *p_czsq, *p_P, *p_lv;
    int* p_idx;
    cudaGetSymbolAddress((void**)&p_cz, g_cz);
    cudaGetSymbolAddress((void**)&p_esq, g_esq);
    cudaGetSymbolAddress((void**)&p_esq_mm, g_esq_mm);
    cudaGetSymbolAddress((void**)&p_czsq, g_czsq);
    cudaGetSymbolAddress((void**)&p_idx, g_idx);
    cudaGetSymbolAddress((void**)&p_P, g_P);
    cudaGetSymbolAddress((void**)&p_lv, g_lv);

    static cudaStream_t sB = 0;
    static cudaEvent_t evFork, evEnd, evA[NCHUNK];
    static bool init_done = false;
    if (!init_done) {
        if (cudaStreamCreateWithFlags(&sB, cudaStreamNonBlocking) != cudaSuccess) sB = 0;
        cudaEventCreateWithFlags(&evFork, cudaEventDisableTiming);
        cudaEventCreateWithFlags(&evEnd, cudaEventDisableTiming);
        for (int c = 0; c < NCHUNK; c++)
            cudaEventCreateWithFlags(&evA[c], cudaEventDisableTiming);
        init_done = true;
    }

    int zoff = out_size - kM1 * kD;
    float* zq = out + (zoff > 0 ? zoff : 0);
    bool do_loss = (zoff >= 1);
    bool do_zq = (out_size >= kM1 * kD);

    // fork sB from the capture stream
    cudaEventRecord(evFork, 0);
    cudaStreamWaitEvent(sB, evFork, 0);

    // sB: codebook-side precomputes (independent of cz)
    pgemm_kernel<<<dim3(kD / 128, kNE / 128, kCH), 256, 0, sB>>>(E, W1, p_P);
    rowsq4_kernel<<<kNE / 32, 256, 0, sB>>>(E, p_esq);
    esq_minmax_kernel<<<1, 256, 0, sB>>>(p_esq, p_esq_mm);

    // stream0: gemm0 chunks; sB consumes each chunk (rowsq -> argmax -> gather)
    for (int c = 0; c < NCHUNK; c++) {
        gemm0_kernel<<<dim3(kD / 128, M1C / 128), 256>>>(
            z + (size_t)c * M1C * kD, W0, b0, p_cz + (size_t)c * M1C * kD);
        cudaEventRecord(evA[c], 0);
        cudaStreamWaitEvent(sB, evA[c], 0);
        rowsq4_kernel<<<MRC / 32, 256, 0, sB>>>(p_cz + (size_t)c * M1C * kD,
                                                p_czsq + (size_t)c * MRC);
        argmax5_kernel<<<MRC, 128, 0, sB>>>(p_cz + (size_t)c * M1C * kD, E,
                                            p_czsq + (size_t)c * MRC, p_esq, p_esq_mm,
                                            p_idx + (size_t)c * MRC,
                                            p_lv + (size_t)c * MRC, c * MRC);
        if (do_zq)
            gather_zq_kernel<<<M1C, 256, 0, sB>>>(p_P, p_idx + (size_t)c * MRC, b1,
                                                  zq + (size_t)c * M1C * kD);
    }
    if (do_loss)
        lvsum_kernel<<<1, 1024, 0, sB>>>(p_lv, out);

    // join sB back into the capture stream
    cudaEventRecord(evEnd, sB);
    cudaStreamWaitEvent(0, evEnd, 0);
}